// round 2
// baseline (speedup 1.0000x reference)
#include <cuda_runtime.h>

// ---------------------------------------------------------------------------
// fp4 (bitsandbytes) dequant + GEMV:  y[4, M] = x[4, N] @ W[M, N]^T + bias
//   qweight: numel/2 int32, each holding ONE byte (two 4-bit codebook indices)
//   absmax : per-64-element block scale
//   code   : 16-entry fp4 codebook
// ---------------------------------------------------------------------------

static __device__ __forceinline__ unsigned long long pk2(float lo, float hi) {
    unsigned long long r;
    asm("mov.b64 %0, {%1, %2};" : "=l"(r) : "f"(lo), "f"(hi));
    return r;
}
static __device__ __forceinline__ void up2(unsigned long long v, float& lo, float& hi) {
    asm("mov.b64 {%0, %1}, %2;" : "=f"(lo), "=f"(hi) : "l"(v));
}
static __device__ __forceinline__ unsigned long long f2fma(unsigned long long a,
                                                           unsigned long long b,
                                                           unsigned long long c) {
    unsigned long long d;
    asm("fma.rn.f32x2 %0, %1, %2, %3;" : "=l"(d) : "l"(a), "l"(b), "l"(c));
    return d;
}
static __device__ __forceinline__ unsigned long long f2add(unsigned long long a,
                                                           unsigned long long b) {
    unsigned long long d;
    asm("add.rn.f32x2 %0, %1, %2;" : "=l"(d) : "l"(a), "l"(b));
    return d;
}

constexpr int MD  = 8192;   // out features
constexpr int ND  = 8192;   // in features
constexpr int RW  = 4;      // rows per warp
constexpr int WPB = 8;      // warps per block
constexpr int RPB = RW * WPB;  // 32 rows per block

__global__ void __launch_bounds__(256, 2)
fp4_gemv(const float* __restrict__ x, const int* __restrict__ qw,
         const float* __restrict__ am, const float* __restrict__ code,
         const float* __restrict__ bias, float* __restrict__ out)
{
    const int lane = threadIdx.x & 31;
    const int wid  = threadIdx.x >> 5;

    // Register-resident codebook: lane l holds code[l & 15]; decode = shfl by nibble.
    const float creg = code[lane & 15];

    const int row0 = blockIdx.x * RPB + wid * RW;

    unsigned long long a01[RW], a23[RW];
#pragma unroll
    for (int r = 0; r < RW; r++) { a01[r] = 0ull; a23[r] = 0ull; }

    const int4* q4 = reinterpret_cast<const int4*>(qw);
    const int ldq = ND / 8;    // int4 per row (1024)
    const int lda = ND / 64;   // absmax blocks per row (128)

    // Each lane owns int4 index li = it*32 + lane within each of its 4 rows.
    // One int4 = 4 int32 = 4 bytes of packed data = 8 weights = n in [8*li, 8*li+8).
    for (int it = 0; it < (ND / 8) / 32; ++it) {
        const int li = it * 32 + lane;
        const int nb = li * 8;

        // x window: 8 consecutive n for all 4 batches, packed as (b0,b1) / (b2,b3).
        unsigned long long x01[8], x23[8];
        {
            const float4 a0 = *reinterpret_cast<const float4*>(x + 0 * ND + nb);
            const float4 b0 = *reinterpret_cast<const float4*>(x + 0 * ND + nb + 4);
            const float4 a1 = *reinterpret_cast<const float4*>(x + 1 * ND + nb);
            const float4 b1 = *reinterpret_cast<const float4*>(x + 1 * ND + nb + 4);
            const float4 a2 = *reinterpret_cast<const float4*>(x + 2 * ND + nb);
            const float4 b2 = *reinterpret_cast<const float4*>(x + 2 * ND + nb + 4);
            const float4 a3 = *reinterpret_cast<const float4*>(x + 3 * ND + nb);
            const float4 b3 = *reinterpret_cast<const float4*>(x + 3 * ND + nb + 4);
            x01[0] = pk2(a0.x, a1.x); x01[1] = pk2(a0.y, a1.y);
            x01[2] = pk2(a0.z, a1.z); x01[3] = pk2(a0.w, a1.w);
            x01[4] = pk2(b0.x, b1.x); x01[5] = pk2(b0.y, b1.y);
            x01[6] = pk2(b0.z, b1.z); x01[7] = pk2(b0.w, b1.w);
            x23[0] = pk2(a2.x, a3.x); x23[1] = pk2(a2.y, a3.y);
            x23[2] = pk2(a2.z, a3.z); x23[3] = pk2(a2.w, a3.w);
            x23[4] = pk2(b2.x, b3.x); x23[5] = pk2(b2.y, b3.y);
            x23[6] = pk2(b2.z, b3.z); x23[7] = pk2(b2.w, b3.w);
        }

#pragma unroll
        for (int r = 0; r < RW; r++) {
            const int row = row0 + r;
            const int4 q  = __ldg(&q4[row * ldq + li]);
            // absmax block index for the whole window: (row*N + 8*li)/64
            const float s = __ldg(&am[row * lda + (li >> 3)]);
            const int bs[4] = { q.x, q.y, q.z, q.w };
#pragma unroll
            for (int j = 0; j < 4; j++) {
                const int  b   = bs[j] & 255;
                const float chi = __shfl_sync(0xffffffffu, creg, b >> 4);   // element n=2i
                const float clo = __shfl_sync(0xffffffffu, creg, b & 15);   // element n=2i+1
                const float w0 = chi * s;
                const float w1 = clo * s;
                const unsigned long long s0 = pk2(w0, w0);
                const unsigned long long s1 = pk2(w1, w1);
                a01[r] = f2fma(s0, x01[2 * j],     a01[r]);
                a01[r] = f2fma(s1, x01[2 * j + 1], a01[r]);
                a23[r] = f2fma(s0, x23[2 * j],     a23[r]);
                a23[r] = f2fma(s1, x23[2 * j + 1], a23[r]);
            }
        }
    }

    // Butterfly reduction over lanes (packed f32x2 adds).
#pragma unroll
    for (int r = 0; r < RW; r++) {
#pragma unroll
        for (int off = 16; off > 0; off >>= 1) {
            a01[r] = f2add(a01[r], __shfl_xor_sync(0xffffffffu, a01[r], off));
            a23[r] = f2add(a23[r], __shfl_xor_sync(0xffffffffu, a23[r], off));
        }
    }

#pragma unroll
    for (int r = 0; r < RW; r++) {
        if (lane == r) {
            const int row = row0 + r;
            float y0, y1, y2, y3;
            up2(a01[r], y0, y1);
            up2(a23[r], y2, y3);
            const float bb = bias[row];
            out[0 * MD + row] = y0 + bb;
            out[1 * MD + row] = y1 + bb;
            out[2 * MD + row] = y2 + bb;
            out[3 * MD + row] = y3 + bb;
        }
    }
}

extern "C" void kernel_launch(void* const* d_in, const int* in_sizes, int n_in,
                              void* d_out, int out_size)
{
    const float* x    = (const float*)d_in[0];
    const int*   qw   = (const int*)d_in[1];
    const float* am   = (const float*)d_in[2];
    const float* code = (const float*)d_in[3];
    const float* bias = (const float*)d_in[4];
    float*       out  = (float*)d_out;

    fp4_gemv<<<MD / RPB, 256>>>(x, qw, am, code, bias, out);
}